// round 15
// baseline (speedup 1.0000x reference)
#include <cuda_runtime.h>
#include <cstdint>

#define LOG2E_F 1.4426950408889634f
#define RSTRIDE 272u                     // bytes per bf16 row (136 bf16, 17×16B: conflict-free)

// ---- shared memory byte offsets ----
#define OFF_AH  0u
#define OFF_AL  (OFF_AH + 128u * RSTRIDE)    // 34816
#define OFF_BH  (OFF_AL + 128u * RSTRIDE)    // 69632
#define OFF_BL  (OFF_BH + 128u * RSTRIDE)    // 104448
#define OFF_SA  (OFF_BL + 128u * RSTRIDE)    // 139264
#define OFF_SQA (OFF_SA + 512u)
#define OFF_SB  (OFF_SQA + 512u)
#define OFF_SQB (OFF_SB + 512u)
#define OFF_SC  (OFF_SQB + 512u)             // 16 scalars
#define OFF_V   (OFF_SC + 64u)               // 4*128 floats = 2048 B
#define OFF_PSM (OFF_V + 2048u)              // 4k * 128 rows * 2 col-halves = 4096 B
#define OFF_PART (OFF_PSM + 4096u)           // 2048 * float4 partials = 32768 B
#define SMEM_BYTES (OFF_PART + 32768u)       // 180288

static __device__ __forceinline__ uint32_t smem_u32(const void* p) {
    uint32_t a;
    asm("{ .reg .u64 t; cvta.to.shared.u64 t, %1; cvt.u32.u64 %0, t; }" : "=r"(a) : "l"(p));
    return a;
}

static __device__ __forceinline__ uint32_t cvt2bf(float x1, float x0) {
    uint32_t r;
    asm("cvt.rn.bf16x2.f32 %0, %1, %2;" : "=r"(r) : "f"(x1), "f"(x0));
    return r;
}

#define LDMX4(r, addr) \
    asm volatile("ldmatrix.sync.aligned.m8n8.x4.shared.b16 {%0,%1,%2,%3}, [%4];" \
        : "=r"((r)[0]), "=r"((r)[1]), "=r"((r)[2]), "=r"((r)[3]) : "r"(addr))

#define MMA16816(d, a, b0, b1) \
    asm volatile("mma.sync.aligned.m16n8k16.row.col.f32.bf16.bf16.f32 " \
        "{%0,%1,%2,%3}, {%4,%5,%6,%7}, {%8,%9}, {%0,%1,%2,%3};" \
        : "+f"((d)[0]), "+f"((d)[1]), "+f"((d)[2]), "+f"((d)[3]) \
        : "r"((a)[0]), "r"((a)[1]), "r"((a)[2]), "r"((a)[3]), "r"(b0), "r"(b1))

#define PAIR_BAR(mw) \
    asm volatile("bar.sync %0, %1;" :: "r"(1 + (mw)), "r"(64) : "memory")

// deg-6 Taylor for exp(kv), kv in [0,1] — FMA pipe (proven rel ~1.2e-6)
static __device__ __forceinline__ float taylor_exp(float kv) {
    float e = 1.3888889e-3f;                   // 1/720
    e = fmaf(e, kv, 8.3333333e-3f);            // 1/120
    e = fmaf(e, kv, 4.1666667e-2f);            // 1/24
    e = fmaf(e, kv, 1.6666667e-1f);            // 1/6
    e = fmaf(e, kv, 0.5f);
    e = fmaf(e, kv, 1.0f);
    e = fmaf(e, kv, 1.0f);
    return e;
}

// MUFU path: kv = 2^t via ex2 (ftz: t<-126 -> 0 -> E=1, correct limit)
static __device__ __forceinline__ float dexp_mufu(float t) {
    float kv;
    asm("ex2.approx.ftz.f32 %0, %1;" : "=f"(kv) : "f"(t));
    return taylor_exp(kv);
}

// FMA/ALU path: kv = 2^t via magic-number split + deg-5 poly (R4-proven, abs err ~3e-7)
static __device__ __forceinline__ float dexp_poly(float t) {
    t = fmaxf(t, -126.f);
    float ft = t + 12582912.f;                 // 1.5 * 2^23
    float rr = t - (ft - 12582912.f);          // in [-0.5, 0.5]
    float p = 1.3333558e-3f;
    p = fmaf(p, rr, 9.6181291e-3f);
    p = fmaf(p, rr, 5.5504109e-2f);
    p = fmaf(p, rr, 2.4022651e-1f);
    p = fmaf(p, rr, 6.9314718e-1f);
    p = fmaf(p, rr, 1.0f);
    uint32_t ib = ((uint32_t)__float_as_int(ft) << 23) + 0x3F800000u;
    float kv = p * __uint_as_float(ib);        // in (0, 1]
    return taylor_exp(kv);
}

static __device__ __forceinline__ void conv8(float4 v0, float4 v1, uint32_t* h, uint32_t* l) {
    float v[8] = {v0.x, v0.y, v0.z, v0.w, v1.x, v1.y, v1.z, v1.w};
    #pragma unroll
    for (int e = 0; e < 4; e++) {
        float x0 = v[2 * e], x1 = v[2 * e + 1];
        uint32_t hp = cvt2bf(x1, x0);
        float hf0 = __uint_as_float(hp << 16);
        float hf1 = __uint_as_float(hp & 0xFFFF0000u);
        h[e] = hp;
        l[e] = cvt2bf(x1 - hf1, x0 - hf0);
    }
}

static __device__ __forceinline__ void sum8(float4 v0, float4 v1, float& s, float& s2) {
    s += ((v0.x + v0.y) + (v0.z + v0.w)) + ((v1.x + v1.y) + (v1.z + v1.w));
    s2 = fmaf(v0.x, v0.x, s2); s2 = fmaf(v0.y, v0.y, s2);
    s2 = fmaf(v0.z, v0.z, s2); s2 = fmaf(v0.w, v0.w, s2);
    s2 = fmaf(v1.x, v1.x, s2); s2 = fmaf(v1.y, v1.y, s2);
    s2 = fmaf(v1.z, v1.z, s2); s2 = fmaf(v1.w, v1.w, s2);
}

extern __shared__ char smc[];

__global__ void __launch_bounds__(512, 1)
cm_rbf_w16d_kernel(const float* __restrict__ x1,
                   const float* __restrict__ x2,
                   const float* __restrict__ sigmas,
                   const float* __restrict__ means,
                   const float* __restrict__ sigma_params,
                   float* __restrict__ out)
{
    const int n   = blockIdx.x;
    const int tid = threadIdx.x;
    const int wid = tid >> 5;
    const int lid = tid & 31;
    const int mw  = wid >> 1;            // row group (16 rows)
    const int cw  = wid & 1;             // column half (64 cols)
    const uint32_t sbase = smem_u32(smc);

    const float* ga = x1 + (size_t)n * 16384;
    const float* gb = x2 + (size_t)n * 16384;

    float* SAp  = (float*)(smc + OFF_SA);
    float* SQAp = (float*)(smc + OFF_SQA);
    float4* part = (float4*)(smc + OFF_PART);

    // ---- Phase 1: fp32 -> bf16 hi/lo into smem; per-chunk stats -> packed partials ----
    // All 4 LDG.128 issued before any conversion (MLP 4).
    #pragma unroll
    for (int q = 0; q < 4; q++) {
        int g = tid + (q << 9);
        int row = g >> 4;
        int ch  = g & 15;
        uint32_t so = (uint32_t)row * RSTRIDE + (uint32_t)ch * 16u;

        const float4* pa = (const float4*)(ga + row * 128 + ch * 8);
        const float4* pb = (const float4*)(gb + row * 128 + ch * 8);
        float4 a0 = pa[0], a1 = pa[1];
        float4 b0 = pb[0], b1 = pb[1];

        float sA = 0.f, s2A = 0.f, sB = 0.f, s2B = 0.f;
        sum8(a0, a1, sA, s2A);
        sum8(b0, b1, sB, s2B);

        uint32_t h[4], l[4];
        conv8(a0, a1, h, l);
        *(uint4*)(smc + OFF_AH + so) = make_uint4(h[0], h[1], h[2], h[3]);
        *(uint4*)(smc + OFF_AL + so) = make_uint4(l[0], l[1], l[2], l[3]);
        conv8(b0, b1, h, l);
        *(uint4*)(smc + OFF_BH + so) = make_uint4(h[0], h[1], h[2], h[3]);
        *(uint4*)(smc + OFF_BL + so) = make_uint4(l[0], l[1], l[2], l[3]);

        part[g] = make_float4(sA, s2A, sB, s2B);
    }
    if (tid == 0) {
        float* sc = (float*)(smc + OFF_SC);
        float iv[4], mx = -3.4e38f;
        #pragma unroll
        for (int k = 0; k < 4; k++) {
            float v = sigma_params[k];
            iv[k] = 1.f / (v * v);
            mx = fmaxf(mx, iv[k]);
        }
        float se = 0.f, ee[4];
        #pragma unroll
        for (int k = 0; k < 4; k++) { ee[k] = __expf(iv[k] - mx); se += ee[k]; }
        #pragma unroll
        for (int k = 0; k < 4; k++) {
            float sg = sigmas[k];
            float P  = 0.5f / (sg * sg);
            sc[k]      = means[k];
            sc[4 + k]  = 2.f * P * LOG2E_F;   // Q'
            sc[8 + k]  = -P * LOG2E_F;        // -P'
            sc[12 + k] = ee[k] / se;          // w_k
        }
    }
    __syncthreads();

    // ---- Phase 2: per-row stat reduce (staggered, <=2-way conflicts) + V_kj ----
    if (tid < 128) {
        const int row = tid;
        float sA = 0.f, s2A = 0.f, sB = 0.f, s2B = 0.f;
        #pragma unroll
        for (int it = 0; it < 16; it++) {
            int c = (it + row) & 15;
            float4 p = part[row * 16 + c];
            sA += p.x; s2A += p.y; sB += p.z; s2B += p.w;
        }
        SAp[row]  = sA;
        SQAp[row] = s2A;

        const float* sc = (const float*)(smc + OFF_SC);
        float* Varr = (float*)(smc + OFF_V);
        #pragma unroll
        for (int k = 0; k < 4; k++) {
            float m = sc[k], nP = sc[8 + k];
            Varr[k * 128 + row] = nP * (fmaf(2.f * m, sB, s2B) + 128.f * m * m);
        }
    }
    __syncthreads();

    // ---- Phase 3: HMMA GEMM. Warp (mw,cw): rows 16mw..+15, cols 64cw..+63. ----
    const int mi = lid >> 3;
    const int ri = lid & 7;
    const uint32_t hi16  = (uint32_t)(mi >> 1) * 16u;
    const uint32_t aoff  = (uint32_t)(16 * mw + (mi & 1) * 8 + ri) * RSTRIDE + hi16;
    const uint32_t brow0 = (uint32_t)(64 * cw + (mi & 1) * 8 + ri);

    float d[8][4];
    #pragma unroll
    for (int t = 0; t < 8; t++)
        #pragma unroll
        for (int e = 0; e < 4; e++) d[t][e] = 0.f;

    const uint32_t Ah = sbase + OFF_AH, Al = sbase + OFF_AL;
    const uint32_t Bh = sbase + OFF_BH, Bl = sbase + OFF_BL;

    #pragma unroll
    for (int kk = 0; kk < 8; kk++) {
        const uint32_t ka = (uint32_t)kk * 32u;
        uint32_t ah[4], al[4];
        LDMX4(ah, Ah + aoff + ka);
        LDMX4(al, Al + aoff + ka);
        #pragma unroll
        for (int ng = 0; ng < 4; ng++) {
            uint32_t boff = ((uint32_t)(ng * 16) + brow0) * RSTRIDE + hi16 + ka;
            uint32_t bh[4], bl[4];
            LDMX4(bh, Bh + boff);
            LDMX4(bl, Bl + boff);
            MMA16816(d[2 * ng],     ah, bh[0], bh[2]);
            MMA16816(d[2 * ng],     ah, bl[0], bl[2]);
            MMA16816(d[2 * ng],     al, bh[0], bh[2]);
            MMA16816(d[2 * ng + 1], ah, bh[1], bh[3]);
            MMA16816(d[2 * ng + 1], ah, bl[1], bl[3]);
            MMA16816(d[2 * ng + 1], al, bh[1], bh[3]);
        }
    }

    // ---- Phase 4: elementwise, both row-halves per k; exp split across MUFU/FMA pipes ----
    const int rq = lid >> 2, cq = lid & 3;
    const int r0 = 16 * mw + rq;
    const int r1 = r0 + 8;
    const float* scp = (const float*)(smc + OFF_SC);
    float* psm = (float*)(smc + OFF_PSM);

    const float sar0 = SAp[r0], sqar0 = SQAp[r0];
    const float sar1 = SAp[r1], sqar1 = SQAp[r1];

    float acc0[16], acc1[16];
    #pragma unroll
    for (int j = 0; j < 16; j++) { acc0[j] = 0.f; acc1[j] = 0.f; }

    #pragma unroll 1
    for (int k = 0; k < 4; k++) {
        float m  = scp[k];
        float Qk = scp[4 + k];
        float nP = scp[8 + k];
        float wk = scp[12 + k];
        float Uk0 = nP * fmaf(-2.f * m, sar0, sqar0);
        float Uk1 = nP * fmaf(-2.f * m, sar1, sqar1);
        const float2* Vp = (const float2*)(smc + OFF_V + (uint32_t)k * 512u)
                           + (32 * cw + cq);

        float ev0[16], ev1[16];
        float ps0 = 0.f, ps1 = 0.f;
        #pragma unroll
        for (int nt = 0; nt < 8; nt++) {
            float2 v2 = Vp[nt * 4];
            float e00, e01, e10, e11;
            if (nt & 1) {
                e00 = dexp_poly(fmaf(Qk, d[nt][0], Uk0 + v2.x));
                e01 = dexp_poly(fmaf(Qk, d[nt][1], Uk0 + v2.y));
                e10 = dexp_poly(fmaf(Qk, d[nt][2], Uk1 + v2.x));
                e11 = dexp_poly(fmaf(Qk, d[nt][3], Uk1 + v2.y));
            } else {
                e00 = dexp_mufu(fmaf(Qk, d[nt][0], Uk0 + v2.x));
                e01 = dexp_mufu(fmaf(Qk, d[nt][1], Uk0 + v2.y));
                e10 = dexp_mufu(fmaf(Qk, d[nt][2], Uk1 + v2.x));
                e11 = dexp_mufu(fmaf(Qk, d[nt][3], Uk1 + v2.y));
            }
            ev0[2 * nt]     = e00;
            ev0[2 * nt + 1] = e01;
            ev1[2 * nt]     = e10;
            ev1[2 * nt + 1] = e11;
            ps0 += e00 + e01;
            ps1 += e10 + e11;
        }
        ps0 += __shfl_xor_sync(0xFFFFFFFFu, ps0, 1);
        ps0 += __shfl_xor_sync(0xFFFFFFFFu, ps0, 2);
        ps1 += __shfl_xor_sync(0xFFFFFFFFu, ps1, 1);
        ps1 += __shfl_xor_sync(0xFFFFFFFFu, ps1, 2);

        if (cq == 0) {
            psm[(k * 128 + r0) * 2 + cw] = ps0;
            psm[(k * 128 + r1) * 2 + cw] = ps1;
        }
        PAIR_BAR(mw);
        float S0 = psm[(k * 128 + r0) * 2] + psm[(k * 128 + r0) * 2 + 1];
        float S1 = psm[(k * 128 + r1) * 2] + psm[(k * 128 + r1) * 2 + 1];
        float cc0 = __fdividef(wk, S0);
        float cc1 = __fdividef(wk, S1);
        #pragma unroll
        for (int j = 0; j < 16; j++) {
            acc0[j] = fmaf(cc0, ev0[j], acc0[j]);
            acc1[j] = fmaf(cc1, ev1[j], acc1[j]);
        }
    }

    // ---- Phase 5: store both rows ----
    float* go0 = out + (size_t)n * 16384 + (size_t)r0 * 128 + 64 * cw;
    float* go1 = out + (size_t)n * 16384 + (size_t)r1 * 128 + 64 * cw;
    #pragma unroll
    for (int nt = 0; nt < 8; nt++) {
        *(float2*)(go0 + nt * 8 + 2 * cq) = make_float2(acc0[2 * nt], acc0[2 * nt + 1]);
        *(float2*)(go1 + nt * 8 + 2 * cq) = make_float2(acc1[2 * nt], acc1[2 * nt + 1]);
    }
}

extern "C" void kernel_launch(void* const* d_in, const int* in_sizes, int n_in,
                              void* d_out, int out_size)
{
    (void)n_in; (void)out_size;
    const float* x1 = (const float*)d_in[0];
    const float* x2 = (const float*)d_in[1];
    const float* sg = (const float*)d_in[2];
    const float* mn = (const float*)d_in[3];
    const float* sp = (const float*)d_in[4];
    float* out = (float*)d_out;

    int N = in_sizes[0] / 16384;   // 128

    cudaFuncSetAttribute(cm_rbf_w16d_kernel,
                         cudaFuncAttributeMaxDynamicSharedMemorySize, SMEM_BYTES);

    cm_rbf_w16d_kernel<<<N, 512, SMEM_BYTES>>>(x1, x2, sg, mn, sp, out);
}

// round 17
// speedup vs baseline: 1.2548x; 1.2548x over previous
#include <cuda_runtime.h>
#include <cuda_fp16.h>
#include <cstdint>

#define LOG2E_F 1.4426950408889634f
#define RSTRIDE 272u                     // bytes per f16 row (136 halves, 17×16B: conflict-free)

// ---- shared memory byte offsets ----
#define OFF_AH  0u
#define OFF_AL  34816u
#define OFF_BH  69632u                   // B hi only (2-pass fp16 needs no B-lo)
#define OFF_SA  104448u                  // 128 f
#define OFF_SQA (OFF_SA + 512u)
#define OFF_SC  (OFF_SQA + 512u)         // 16 scalars
#define OFF_V   (OFF_SC + 64u)           // 4*128 floats = 2048 B
#define OFF_PSM (OFF_V + 2048u)          // 4k * 128 rows * 2 col-halves = 4096 B
#define OFF_PART (OFF_PSM + 4096u)       // 2048 * float4 partials = 32768 B
#define SMEM_BYTES (OFF_PART + 32768u)   // 144448

static __device__ __forceinline__ uint32_t smem_u32(const void* p) {
    uint32_t a;
    asm("{ .reg .u64 t; cvta.to.shared.u64 t, %1; cvt.u32.u64 %0, t; }" : "=r"(a) : "l"(p));
    return a;
}

// pack two fp32 -> f16x2 (x0 lower half, x1 upper half), round-to-nearest
static __device__ __forceinline__ uint32_t cvt2h(float x1, float x0) {
    uint32_t r;
    asm("cvt.rn.f16x2.f32 %0, %1, %2;" : "=r"(r) : "f"(x1), "f"(x0));
    return r;
}

#define LDMX4(r, addr) \
    asm volatile("ldmatrix.sync.aligned.m8n8.x4.shared.b16 {%0,%1,%2,%3}, [%4];" \
        : "=r"((r)[0]), "=r"((r)[1]), "=r"((r)[2]), "=r"((r)[3]) : "r"(addr))

#define MMA16816H(d, a, b0, b1) \
    asm volatile("mma.sync.aligned.m16n8k16.row.col.f32.f16.f16.f32 " \
        "{%0,%1,%2,%3}, {%4,%5,%6,%7}, {%8,%9}, {%0,%1,%2,%3};" \
        : "+f"((d)[0]), "+f"((d)[1]), "+f"((d)[2]), "+f"((d)[3]) \
        : "r"((a)[0]), "r"((a)[1]), "r"((a)[2]), "r"((a)[3]), "r"(b0), "r"(b1))

#define PAIR_BAR(mw) \
    asm volatile("bar.sync %0, %1;" :: "r"(1 + (mw)), "r"(64) : "memory")

// E = exp(2^t). One MUFU for 2^t (ftz: t<-126 -> kv=0 -> E=1, correct limit),
// then deg-6 Taylor for exp(kv), kv ~ (0,1] — FMA pipe (16.9us-proven config).
static __device__ __forceinline__ float dexp(float t) {
    float kv;
    asm("ex2.approx.ftz.f32 %0, %1;" : "=f"(kv) : "f"(t));
    float e = 1.3888889e-3f;                   // 1/720
    e = fmaf(e, kv, 8.3333333e-3f);            // 1/120
    e = fmaf(e, kv, 4.1666667e-2f);            // 1/24
    e = fmaf(e, kv, 1.6666667e-1f);            // 1/6
    e = fmaf(e, kv, 0.5f);
    e = fmaf(e, kv, 1.0f);
    e = fmaf(e, kv, 1.0f);
    return e;
}

// split 8 fp32 into f16 hi / f16 lo packed words (hi + lo == x to ~2^-24 rel)
static __device__ __forceinline__ void conv8h(float4 v0, float4 v1, uint32_t* h, uint32_t* l) {
    float v[8] = {v0.x, v0.y, v0.z, v0.w, v1.x, v1.y, v1.z, v1.w};
    #pragma unroll
    for (int e = 0; e < 4; e++) {
        uint32_t hp = cvt2h(v[2 * e + 1], v[2 * e]);
        float2 hf = __half22float2(*reinterpret_cast<const __half2*>(&hp));
        h[e] = hp;
        l[e] = cvt2h(v[2 * e + 1] - hf.y, v[2 * e] - hf.x);
    }
}

// hi-only conversion for B
static __device__ __forceinline__ void conv8hh(float4 v0, float4 v1, uint32_t* h) {
    h[0] = cvt2h(v0.y, v0.x);
    h[1] = cvt2h(v0.w, v0.z);
    h[2] = cvt2h(v1.y, v1.x);
    h[3] = cvt2h(v1.w, v1.z);
}

static __device__ __forceinline__ void sum8(float4 v0, float4 v1, float& s, float& s2) {
    s += ((v0.x + v0.y) + (v0.z + v0.w)) + ((v1.x + v1.y) + (v1.z + v1.w));
    s2 = fmaf(v0.x, v0.x, s2); s2 = fmaf(v0.y, v0.y, s2);
    s2 = fmaf(v0.z, v0.z, s2); s2 = fmaf(v0.w, v0.w, s2);
    s2 = fmaf(v1.x, v1.x, s2); s2 = fmaf(v1.y, v1.y, s2);
    s2 = fmaf(v1.z, v1.z, s2); s2 = fmaf(v1.w, v1.w, s2);
}

extern __shared__ char smc[];

__global__ void __launch_bounds__(512, 1)
cm_rbf_h2_kernel(const float* __restrict__ x1,
                 const float* __restrict__ x2,
                 const float* __restrict__ sigmas,
                 const float* __restrict__ means,
                 const float* __restrict__ sigma_params,
                 float* __restrict__ out)
{
    const int n   = blockIdx.x;
    const int tid = threadIdx.x;
    const int wid = tid >> 5;
    const int lid = tid & 31;
    const int mw  = wid >> 1;            // row group (16 rows)
    const int cw  = wid & 1;             // column half (64 cols)
    const uint32_t sbase = smem_u32(smc);

    const float* ga = x1 + (size_t)n * 16384;
    const float* gb = x2 + (size_t)n * 16384;

    float* SAp  = (float*)(smc + OFF_SA);
    float* SQAp = (float*)(smc + OFF_SQA);
    float4* part = (float4*)(smc + OFF_PART);

    // ---- Phase 1: fp32 -> f16 hi/lo (A) and f16 hi (B); stats from exact fp32 ----
    #pragma unroll
    for (int q = 0; q < 4; q++) {
        int g = tid + (q << 9);
        int row = g >> 4;
        int ch  = g & 15;
        uint32_t so = (uint32_t)row * RSTRIDE + (uint32_t)ch * 16u;

        const float4* pa = (const float4*)(ga + row * 128 + ch * 8);
        const float4* pb = (const float4*)(gb + row * 128 + ch * 8);
        float4 a0 = pa[0], a1 = pa[1];
        float4 b0 = pb[0], b1 = pb[1];

        float sA = 0.f, s2A = 0.f, sB = 0.f, s2B = 0.f;
        sum8(a0, a1, sA, s2A);
        sum8(b0, b1, sB, s2B);

        uint32_t h[4], l[4];
        conv8h(a0, a1, h, l);
        *(uint4*)(smc + OFF_AH + so) = make_uint4(h[0], h[1], h[2], h[3]);
        *(uint4*)(smc + OFF_AL + so) = make_uint4(l[0], l[1], l[2], l[3]);
        conv8hh(b0, b1, h);
        *(uint4*)(smc + OFF_BH + so) = make_uint4(h[0], h[1], h[2], h[3]);

        part[g] = make_float4(sA, s2A, sB, s2B);
    }
    if (tid == 0) {
        float* sc = (float*)(smc + OFF_SC);
        float iv[4], mx = -3.4e38f;
        #pragma unroll
        for (int k = 0; k < 4; k++) {
            float v = sigma_params[k];
            iv[k] = 1.f / (v * v);
            mx = fmaxf(mx, iv[k]);
        }
        float se = 0.f, ee[4];
        #pragma unroll
        for (int k = 0; k < 4; k++) { ee[k] = __expf(iv[k] - mx); se += ee[k]; }
        #pragma unroll
        for (int k = 0; k < 4; k++) {
            float sg = sigmas[k];
            float P  = 0.5f / (sg * sg);
            sc[k]      = means[k];
            sc[4 + k]  = 2.f * P * LOG2E_F;   // Q'
            sc[8 + k]  = -P * LOG2E_F;        // -P'
            sc[12 + k] = ee[k] / se;          // w_k
        }
    }
    __syncthreads();

    // ---- Phase 2: per-row stat reduce (staggered, <=2-way conflicts) + V_kj ----
    if (tid < 128) {
        const int row = tid;
        float sA = 0.f, s2A = 0.f, sB = 0.f, s2B = 0.f;
        #pragma unroll
        for (int it = 0; it < 16; it++) {
            int c = (it + row) & 15;
            float4 p = part[row * 16 + c];
            sA += p.x; s2A += p.y; sB += p.z; s2B += p.w;
        }
        SAp[row]  = sA;
        SQAp[row] = s2A;

        const float* sc = (const float*)(smc + OFF_SC);
        float* Varr = (float*)(smc + OFF_V);
        #pragma unroll
        for (int k = 0; k < 4; k++) {
            float m = sc[k], nP = sc[8 + k];
            Varr[k * 128 + row] = nP * (fmaf(2.f * m, sB, s2B) + 128.f * m * m);
        }
    }
    __syncthreads();

    // ---- Phase 3: fp16 2-pass HMMA. Warp (mw,cw): rows 16mw..+15, cols 64cw..+63. ----
    // dot = Ah*Bh + Al*Bh = A*Bh; dropped term A*(B-Bh): dot err ~1.6e-3 abs (OK)
    const int mi = lid >> 3;
    const int ri = lid & 7;
    const uint32_t hi16  = (uint32_t)(mi >> 1) * 16u;
    const uint32_t aoff  = (uint32_t)(16 * mw + (mi & 1) * 8 + ri) * RSTRIDE + hi16;
    const uint32_t brow0 = (uint32_t)(64 * cw + (mi & 1) * 8 + ri);

    float d[8][4];
    #pragma unroll
    for (int t = 0; t < 8; t++)
        #pragma unroll
        for (int e = 0; e < 4; e++) d[t][e] = 0.f;

    const uint32_t Ah = sbase + OFF_AH, Al = sbase + OFF_AL;
    const uint32_t Bh = sbase + OFF_BH;

    #pragma unroll
    for (int kk = 0; kk < 8; kk++) {
        const uint32_t ka = (uint32_t)kk * 32u;
        uint32_t ah[4], al[4];
        LDMX4(ah, Ah + aoff + ka);
        LDMX4(al, Al + aoff + ka);
        #pragma unroll
        for (int ng = 0; ng < 4; ng++) {
            uint32_t boff = ((uint32_t)(ng * 16) + brow0) * RSTRIDE + hi16 + ka;
            uint32_t bh[4];
            LDMX4(bh, Bh + boff);
            MMA16816H(d[2 * ng],     ah, bh[0], bh[2]);
            MMA16816H(d[2 * ng],     al, bh[0], bh[2]);
            MMA16816H(d[2 * ng + 1], ah, bh[1], bh[3]);
            MMA16816H(d[2 * ng + 1], al, bh[1], bh[3]);
        }
    }

    // ---- Phase 4: elementwise, both row-halves per k (R13 16.9us-proven structure) ----
    const int rq = lid >> 2, cq = lid & 3;
    const int r0 = 16 * mw + rq;
    const int r1 = r0 + 8;
    const float* scp = (const float*)(smc + OFF_SC);
    float* psm = (float*)(smc + OFF_PSM);

    const float sar0 = SAp[r0], sqar0 = SQAp[r0];
    const float sar1 = SAp[r1], sqar1 = SQAp[r1];

    float acc0[16], acc1[16];
    #pragma unroll
    for (int j = 0; j < 16; j++) { acc0[j] = 0.f; acc1[j] = 0.f; }

    #pragma unroll 1
    for (int k = 0; k < 4; k++) {
        float m  = scp[k];
        float Qk = scp[4 + k];
        float nP = scp[8 + k];
        float wk = scp[12 + k];
        float Uk0 = nP * fmaf(-2.f * m, sar0, sqar0);
        float Uk1 = nP * fmaf(-2.f * m, sar1, sqar1);
        const float2* Vp = (const float2*)(smc + OFF_V + (uint32_t)k * 512u)
                           + (32 * cw + cq);

        float ev0[16], ev1[16];
        float ps0 = 0.f, ps1 = 0.f;
        #pragma unroll
        for (int nt = 0; nt < 8; nt++) {
            float2 v2 = Vp[nt * 4];
            float e00 = dexp(fmaf(Qk, d[nt][0], Uk0 + v2.x));
            float e01 = dexp(fmaf(Qk, d[nt][1], Uk0 + v2.y));
            float e10 = dexp(fmaf(Qk, d[nt][2], Uk1 + v2.x));
            float e11 = dexp(fmaf(Qk, d[nt][3], Uk1 + v2.y));
            ev0[2 * nt]     = e00;
            ev0[2 * nt + 1] = e01;
            ev1[2 * nt]     = e10;
            ev1[2 * nt + 1] = e11;
            ps0 += e00 + e01;
            ps1 += e10 + e11;
        }
        ps0 += __shfl_xor_sync(0xFFFFFFFFu, ps0, 1);
        ps0 += __shfl_xor_sync(0xFFFFFFFFu, ps0, 2);
        ps1 += __shfl_xor_sync(0xFFFFFFFFu, ps1, 1);
        ps1 += __shfl_xor_sync(0xFFFFFFFFu, ps1, 2);

        if (cq == 0) {
            psm[(k * 128 + r0) * 2 + cw] = ps0;
            psm[(k * 128 + r1) * 2 + cw] = ps1;
        }
        PAIR_BAR(mw);
        float S0 = psm[(k * 128 + r0) * 2] + psm[(k * 128 + r0) * 2 + 1];
        float S1 = psm[(k * 128 + r1) * 2] + psm[(k * 128 + r1) * 2 + 1];
        float cc0 = __fdividef(wk, S0);
        float cc1 = __fdividef(wk, S1);
        #pragma unroll
        for (int j = 0; j < 16; j++) {
            acc0[j] = fmaf(cc0, ev0[j], acc0[j]);
            acc1[j] = fmaf(cc1, ev1[j], acc1[j]);
        }
    }

    // ---- Phase 5: store both rows ----
    float* go0 = out + (size_t)n * 16384 + (size_t)r0 * 128 + 64 * cw;
    float* go1 = out + (size_t)n * 16384 + (size_t)r1 * 128 + 64 * cw;
    #pragma unroll
    for (int nt = 0; nt < 8; nt++) {
        *(float2*)(go0 + nt * 8 + 2 * cq) = make_float2(acc0[2 * nt], acc0[2 * nt + 1]);
        *(float2*)(go1 + nt * 8 + 2 * cq) = make_float2(acc1[2 * nt], acc1[2 * nt + 1]);
    }
}

extern "C" void kernel_launch(void* const* d_in, const int* in_sizes, int n_in,
                              void* d_out, int out_size)
{
    (void)n_in; (void)out_size;
    const float* x1 = (const float*)d_in[0];
    const float* x2 = (const float*)d_in[1];
    const float* sg = (const float*)d_in[2];
    const float* mn = (const float*)d_in[3];
    const float* sp = (const float*)d_in[4];
    float* out = (float*)d_out;

    int N = in_sizes[0] / 16384;   // 128

    cudaFuncSetAttribute(cm_rbf_h2_kernel,
                         cudaFuncAttributeMaxDynamicSharedMemorySize, SMEM_BYTES);

    cm_rbf_h2_kernel<<<N, 512, SMEM_BYTES>>>(x1, x2, sg, mn, sp, out);
}